// round 3
// baseline (speedup 1.0000x reference)
#include <cuda_runtime.h>
#include <math.h>

#define B 8
#define OUTD 592002

// ---------------- scratch (device globals; no allocation allowed) ----------------
__device__ float g_bufA[(size_t)B * 128 * 256 * 256];   // 268 MB ping
__device__ float g_bufB[(size_t)B * 128 * 256 * 256];   // 268 MB pong
__device__ float g_skip1[(size_t)B * 64 * 256 * 256];   // conv1 output
__device__ float g_skip2[(size_t)B * 64 * 128 * 128];   // conv2 output
__device__ float g_skip3[(size_t)B * 64 * 64 * 64];     // conv3 output
__device__ float g_w[(size_t)B * OUTD];                 // generated weights
__device__ float g_h2[B * 32];                          // hypernet hidden

// ---------------- f32x2 packed helpers ----------------
__device__ __forceinline__ void fma2(unsigned long long& acc, unsigned long long x,
                                     unsigned long long w)
{
    asm("fma.rn.f32x2 %0, %1, %2, %0;" : "+l"(acc) : "l"(x), "l"(w));
}
__device__ __forceinline__ unsigned long long pack2b(float a)
{
    unsigned long long r;
    asm("mov.b64 %0, {%1, %1};" : "=l"(r) : "f"(a));
    return r;
}
__device__ __forceinline__ float2 unpack2(unsigned long long v)
{
    float2 r;
    asm("mov.b64 {%0, %1}, %2;" : "=f"(r.x), "=f"(r.y) : "l"(v));
    return r;
}

// ---------------- hypernet stage 1: h2 = (hp@W1^T+b1)@W2^T+b2 ----------------
__global__ void hyper1_kernel(const float* __restrict__ hp, const float* __restrict__ W1,
                              const float* __restrict__ b1, const float* __restrict__ W2,
                              const float* __restrict__ b2)
{
    __shared__ float h1[B][32];
    int b = threadIdx.x >> 5;
    int i = threadIdx.x & 31;
    h1[b][i] = hp[b] * W1[i] + b1[i];   // IN_DIM = 1
    __syncthreads();
    float a = b2[i];
#pragma unroll
    for (int k = 0; k < 32; k++) a += h1[b][k] * W2[i * 32 + k];
    g_h2[b * 32 + i] = a;
}

__global__ void zero_l1_kernel(float* __restrict__ l1)
{
    if (threadIdx.x < B) l1[threadIdx.x] = 0.f;
}

// ---------------- hypernet stage 2: w = tanh(h2 @ Wo^T + bo), + L1 reduce ----------------
__global__ void weightgen_kernel(const float* __restrict__ Wo, const float* __restrict__ bo,
                                 float* __restrict__ l1out)
{
    __shared__ float sh2[B * 32];
    __shared__ float wsum[8][B];
    int tid = threadIdx.x;
    sh2[tid] = g_h2[tid];
    __syncthreads();

    int j = blockIdx.x * 256 + tid;
    float s[B];
#pragma unroll
    for (int b = 0; b < B; b++) s[b] = 0.f;

    if (j < OUTD) {
        float wr[32];
        const float* row = Wo + (size_t)j * 32;
#pragma unroll
        for (int i = 0; i < 32; i++) wr[i] = row[i];
        float bj = bo[j];
#pragma unroll
        for (int b = 0; b < B; b++) {
            float a = bj;
#pragma unroll
            for (int i = 0; i < 32; i++) a += wr[i] * sh2[b * 32 + i];
            float w = tanhf(a);
            g_w[(size_t)b * OUTD + j] = w;
            s[b] = fabsf(w);
        }
    }
    int warp = tid >> 5, lane = tid & 31;
#pragma unroll
    for (int b = 0; b < B; b++) {
        float v = s[b];
        for (int off = 16; off > 0; off >>= 1) v += __shfl_xor_sync(0xFFFFFFFFu, v, off);
        if (lane == 0) wsum[warp][b] = v;
    }
    __syncthreads();
    if (tid < B) {
        float a = 0.f;
#pragma unroll
        for (int w = 0; w < 8; w++) a += wsum[w][tid];
        atomicAdd(&l1out[tid], a);
    }
}

// ---------------- NHWC zf -> NCHW x0 ----------------
__global__ void transpose_in_kernel(const float* __restrict__ zf, float* __restrict__ out)
{
    int idx = blockIdx.x * blockDim.x + threadIdx.x;
    int total = B * 2 * 256 * 256;
    if (idx >= total) return;
    int w = idx & 255;
    int h = (idx >> 8) & 255;
    int c = (idx >> 16) & 1;
    int b = idx >> 17;
    out[idx] = zf[(((b * 256 + h) * 256 + w) << 1) + c];
}

// ---------------- 3x3 conv, pad=1, OC=64, per-sample weights ----------------
// Block: 256 threads, 32x32 spatial tile, 16 output channels.
// Each thread: 2x2 pixels x 16 oc; oc paired into f32x2 accumulators.
template<int CIN>
__global__ __launch_bounds__(256, 2) void conv3x3_kernel(
    const float* __restrict__ in, float* __restrict__ out,
    const float* __restrict__ wbuf, int woff, int boff, int H, int relu)
{
    constexpr int CS = (CIN < 4) ? CIN : 4;
    __shared__ float sIn[CS][34 * 34];
    __shared__ float2 sW[CS][8 * 9];      // (oc_even, oc_odd) pairs

    int b   = blockIdx.z;
    int OC0 = blockIdx.y * 16;
    int tiles = H >> 5;
    int ty0 = (blockIdx.x / tiles) << 5;
    int tx0 = (blockIdx.x % tiles) << 5;
    int tid = threadIdx.x;
    int tx = tid & 15, ty = tid >> 4;

    const float* wb  = wbuf + (size_t)b * OUTD;
    const float* inb = in + (size_t)b * CIN * H * H;

    unsigned long long acc[8][4];
#pragma unroll
    for (int i = 0; i < 8; i++)
#pragma unroll
        for (int p = 0; p < 4; p++) acc[i][p] = 0ull;

    for (int c0 = 0; c0 < CIN; c0 += CS) {
        __syncthreads();
        // stage CS input channels (34x34 haloed tiles)
        for (int idx = tid; idx < CS * 1156; idx += 256) {
            int cs = idx / 1156, rem = idx - cs * 1156;
            int r = rem / 34, cc = rem - r * 34;
            int gy = ty0 - 1 + r, gx = tx0 - 1 + cc;
            float v = 0.f;
            if ((unsigned)gy < (unsigned)H && (unsigned)gx < (unsigned)H)
                v = inb[(size_t)(c0 + cs) * H * H + gy * H + gx];
            sIn[cs][rem] = v;
        }
        // stage weights as oc-pairs
        for (int idx = tid; idx < CS * 72; idx += 256) {
            int cs = idx / 72, rem = idx - cs * 72;
            int ocp = rem / 9, k = rem - ocp * 9;
            const float* wp = wb + woff + ((size_t)(OC0 + 2 * ocp) * CIN + (c0 + cs)) * 9 + k;
            sW[cs][rem] = make_float2(wp[0], wp[CIN * 9]);
        }
        __syncthreads();

#pragma unroll
        for (int cs = 0; cs < CS; cs++) {
            float xi[16];
#pragma unroll
            for (int r = 0; r < 4; r++)
#pragma unroll
                for (int cc = 0; cc < 4; cc++)
                    xi[r * 4 + cc] = sIn[cs][(2 * ty + r) * 34 + 2 * tx + cc];
#pragma unroll
            for (int ky = 0; ky < 3; ky++)
#pragma unroll
                for (int kx = 0; kx < 3; kx++) {
                    unsigned long long xx[4];
#pragma unroll
                    for (int py = 0; py < 2; py++)
#pragma unroll
                        for (int px = 0; px < 2; px++)
                            xx[py * 2 + px] = pack2b(xi[(py + ky) * 4 + (px + kx)]);
#pragma unroll
                    for (int ocp = 0; ocp < 8; ocp++) {
                        unsigned long long w =
                            *reinterpret_cast<const unsigned long long*>(&sW[cs][ocp * 9 + ky * 3 + kx]);
#pragma unroll
                        for (int p = 0; p < 4; p++) fma2(acc[ocp][p], xx[p], w);
                    }
                }
        }
    }

    // epilogue: bias + relu + store
#pragma unroll
    for (int ocp = 0; ocp < 8; ocp++) {
        float b0 = wb[boff + OC0 + 2 * ocp];
        float b1 = wb[boff + OC0 + 2 * ocp + 1];
        float* o0 = out + (((size_t)b * 64 + OC0 + 2 * ocp) * H) * H;
        float* o1 = o0 + (size_t)H * H;
#pragma unroll
        for (int py = 0; py < 2; py++)
#pragma unroll
            for (int px = 0; px < 2; px++) {
                float2 v = unpack2(acc[ocp][py * 2 + px]);
                v.x += b0; v.y += b1;
                if (relu) { v.x = fmaxf(v.x, 0.f); v.y = fmaxf(v.y, 0.f); }
                int y = ty0 + 2 * ty + py, x = tx0 + 2 * tx + px;
                o0[y * H + x] = v.x;
                o1[y * H + x] = v.y;
            }
    }
}

// ---------------- 2x2 maxpool ----------------
__global__ void maxpool_kernel(const float* __restrict__ in, float* __restrict__ out, int H, int W)
{
    int Ho = H >> 1, Wo = W >> 1;
    int total = B * 64 * Ho * Wo;
    int idx = blockIdx.x * blockDim.x + threadIdx.x;
    if (idx >= total) return;
    int xo = idx % Wo;
    int yo = (idx / Wo) % Ho;
    int bc = idx / (Wo * Ho);
    const float* p = in + (size_t)bc * H * W + (yo * 2) * W + xo * 2;
    float v = fmaxf(fmaxf(p[0], p[1]), fmaxf(p[W], p[W + 1]));
    out[idx] = v;
}

// ---------------- bilinear upsample x2 (align_corners) -> concat ch 0..63 ----------------
__global__ void upsample_kernel(const float* __restrict__ in, float* __restrict__ out, int H, int W)
{
    int Ho = H * 2, Wo = W * 2;
    int total = B * 64 * Ho * Wo;
    int idx = blockIdx.x * blockDim.x + threadIdx.x;
    if (idx >= total) return;
    int xo = idx % Wo;
    int yo = (idx / Wo) % Ho;
    int c  = (idx / (Wo * Ho)) % 64;
    int b  = idx / (Wo * Ho * 64);

    float ys = (float)yo * (float)(H - 1) / (float)(Ho - 1);
    float xs = (float)xo * (float)(W - 1) / (float)(Wo - 1);
    int y0 = (int)floorf(ys); int y1 = min(y0 + 1, H - 1);
    int x0 = (int)floorf(xs); int x1 = min(x0 + 1, W - 1);
    float wy = ys - (float)y0, wx = xs - (float)x0;

    const float* p = in + ((size_t)b * 64 + c) * H * W;
    float r0 = p[y0 * W + x0] * (1.f - wy) + p[y1 * W + x0] * wy;
    float r1 = p[y0 * W + x1] * (1.f - wy) + p[y1 * W + x1] * wy;
    float v = r0 * (1.f - wx) + r1 * wx;
    out[(((size_t)b * 128 + c) * Ho + yo) * Wo + xo] = v;
}

// ---------------- copy skip into concat buffer ch 64..127 ----------------
__global__ void copyskip_kernel(const float* __restrict__ skip, float* __restrict__ out, int H, int W)
{
    int total = B * 64 * H * W;
    int idx = blockIdx.x * blockDim.x + threadIdx.x;
    if (idx >= total) return;
    int hw = idx % (H * W);
    int c  = (idx / (H * W)) % 64;
    int b  = idx / (H * W * 64);
    out[(((size_t)b * 128 + 64 + c) * H) * W + hw] = skip[idx];
}

// ---------------- final 1x1 conv (64->2) + residual + NCHW->NHWC ----------------
__global__ void final_kernel(const float* __restrict__ in, const float* __restrict__ zf,
                             const float* __restrict__ wbuf, int woff, int boff,
                             float* __restrict__ out)
{
    __shared__ float sw[130];
    int b  = blockIdx.y;
    int tid = threadIdx.x;
    const float* wb = wbuf + (size_t)b * OUTD;
    if (tid < 128) sw[tid] = wb[woff + tid];
    else if (tid < 130) sw[tid] = wb[boff + (tid - 128)];
    __syncthreads();
    int hw = blockIdx.x * 256 + tid;
    const float* inb = in + (size_t)b * 64 * 65536 + hw;
    float a0 = sw[128], a1 = sw[129];
#pragma unroll 8
    for (int c = 0; c < 64; c++) {
        float v = inb[(size_t)c * 65536];
        a0 = fmaf(v, sw[c], a0);
        a1 = fmaf(v, sw[64 + c], a1);
    }
    size_t o = ((size_t)b * 65536 + hw) * 2;
    out[o]     = zf[o]     + a0;
    out[o + 1] = zf[o + 1] + a1;
}

// ---------------- host side ----------------
static const int KOFF[15] = {0, 1152, 38016, 74880, 111744, 148608, 185472, 222336,
                             259200, 332928, 369792, 443520, 480384, 554112, 590976};
static const int CINL[15] = {2, 64, 64, 64, 64, 64, 64, 64, 128, 64, 128, 64, 128, 64, 64};
#define BOFF(i) (591104 + 64 * (i))

static inline void launch_conv(const float* in, float* out, const float* wb,
                               int layer, int H, int relu)
{
    dim3 gs((H / 32) * (H / 32), 4, B);
    int cin = CINL[layer];
    if (cin == 2)
        conv3x3_kernel<2><<<gs, 256>>>(in, out, wb, KOFF[layer], BOFF(layer), H, relu);
    else if (cin == 64)
        conv3x3_kernel<64><<<gs, 256>>>(in, out, wb, KOFF[layer], BOFF(layer), H, relu);
    else
        conv3x3_kernel<128><<<gs, 256>>>(in, out, wb, KOFF[layer], BOFF(layer), H, relu);
}

extern "C" void kernel_launch(void* const* d_in, const int* in_sizes, int n_in,
                              void* d_out, int out_size)
{
    const float* zf = (const float*)d_in[0];
    const float* hp = (const float*)d_in[2];
    const float* W1 = (const float*)d_in[3];
    const float* b1 = (const float*)d_in[4];
    const float* W2 = (const float*)d_in[5];
    const float* b2 = (const float*)d_in[6];
    const float* Wo = (const float*)d_in[7];
    const float* bo = (const float*)d_in[8];
    float* out = (float*)d_out;
    float* l1 = out + (size_t)B * 256 * 256 * 2;

    float *pA, *pB, *pS1, *pS2, *pS3, *pW;
    cudaGetSymbolAddress((void**)&pA,  g_bufA);
    cudaGetSymbolAddress((void**)&pB,  g_bufB);
    cudaGetSymbolAddress((void**)&pS1, g_skip1);
    cudaGetSymbolAddress((void**)&pS2, g_skip2);
    cudaGetSymbolAddress((void**)&pS3, g_skip3);
    cudaGetSymbolAddress((void**)&pW,  g_w);

    hyper1_kernel<<<1, 256>>>(hp, W1, b1, W2, b2);
    zero_l1_kernel<<<1, 32>>>(l1);
    weightgen_kernel<<<(OUTD + 255) / 256, 256>>>(Wo, bo, l1);

    {
        int n = B * 2 * 256 * 256;
        transpose_in_kernel<<<(n + 255) / 256, 256>>>(zf, pB);
    }

    // encoder
    launch_conv(pB, pA, pW, 0, 256, 1);
    launch_conv(pA, pS1, pW, 1, 256, 1);
    { int n = B * 64 * 128 * 128; maxpool_kernel<<<(n + 255) / 256, 256>>>(pS1, pA, 256, 256); }
    launch_conv(pA, pB, pW, 2, 128, 1);
    launch_conv(pB, pS2, pW, 3, 128, 1);
    { int n = B * 64 * 64 * 64;   maxpool_kernel<<<(n + 255) / 256, 256>>>(pS2, pA, 128, 128); }
    launch_conv(pA, pB, pW, 4, 64, 1);
    launch_conv(pB, pS3, pW, 5, 64, 1);
    { int n = B * 64 * 32 * 32;   maxpool_kernel<<<(n + 255) / 256, 256>>>(pS3, pA, 64, 64); }
    launch_conv(pA, pB, pW, 6, 32, 1);
    launch_conv(pB, pA, pW, 7, 32, 1);

    // decoder level 1 (32 -> 64)
    { int n = B * 64 * 64 * 64;   upsample_kernel<<<(n + 255) / 256, 256>>>(pA, pB, 32, 32); }
    { int n = B * 64 * 64 * 64;   copyskip_kernel<<<(n + 255) / 256, 256>>>(pS3, pB, 64, 64); }
    launch_conv(pB, pA, pW, 8, 64, 1);
    launch_conv(pA, pB, pW, 9, 64, 1);

    // decoder level 2 (64 -> 128)
    { int n = B * 64 * 128 * 128; upsample_kernel<<<(n + 255) / 256, 256>>>(pB, pA, 64, 64); }
    { int n = B * 64 * 128 * 128; copyskip_kernel<<<(n + 255) / 256, 256>>>(pS2, pA, 128, 128); }
    launch_conv(pA, pB, pW, 10, 128, 1);
    launch_conv(pB, pA, pW, 11, 128, 1);

    // decoder level 3 (128 -> 256)
    { int n = B * 64 * 256 * 256; upsample_kernel<<<(n + 255) / 256, 256>>>(pA, pB, 128, 128); }
    { int n = B * 64 * 256 * 256; copyskip_kernel<<<(n + 255) / 256, 256>>>(pS1, pB, 256, 256); }
    launch_conv(pB, pA, pW, 12, 256, 1);
    launch_conv(pA, pB, pW, 13, 256, 1);

    {
        dim3 gs(65536 / 256, B);
        final_kernel<<<gs, 256>>>(pB, zf, pW, KOFF[14], BOFF(14), out);
    }
}

// round 4
// speedup vs baseline: 1.1287x; 1.1287x over previous
#include <cuda_runtime.h>
#include <math.h>

#define B 8
#define OUTD 592002

// ---------------- scratch (device globals; no allocation allowed) ----------------
__device__ float g_bufA[(size_t)B * 128 * 256 * 256];   // 268 MB ping
__device__ float g_bufB[(size_t)B * 128 * 256 * 256];   // 268 MB pong
__device__ float g_skip1[(size_t)B * 64 * 256 * 256];   // conv1 output
__device__ float g_skip2[(size_t)B * 64 * 128 * 128];   // conv2 output
__device__ float g_skip3[(size_t)B * 64 * 64 * 64];     // conv3 output
__device__ float g_w[(size_t)B * OUTD];                 // generated weights
__device__ float g_h2[B * 32];                          // hypernet hidden

// ---------------- f32x2 packed helpers ----------------
__device__ __forceinline__ void fma2(unsigned long long& acc, unsigned long long x,
                                     unsigned long long w)
{
    asm("fma.rn.f32x2 %0, %1, %2, %0;" : "+l"(acc) : "l"(x), "l"(w));
}
__device__ __forceinline__ unsigned long long pack2b(float a)
{
    unsigned long long r;
    asm("mov.b64 %0, {%1, %1};" : "=l"(r) : "f"(a));
    return r;
}
__device__ __forceinline__ float2 unpack2(unsigned long long v)
{
    float2 r;
    asm("mov.b64 {%0, %1}, %2;" : "=f"(r.x), "=f"(r.y) : "l"(v));
    return r;
}

// ---------------- hypernet stage 1 (+ zero l1) ----------------
__global__ void hyper1_kernel(const float* __restrict__ hp, const float* __restrict__ W1,
                              const float* __restrict__ b1, const float* __restrict__ W2,
                              const float* __restrict__ b2, float* __restrict__ l1)
{
    __shared__ float h1[B][32];
    int b = threadIdx.x >> 5;
    int i = threadIdx.x & 31;
    if (threadIdx.x < B) l1[threadIdx.x] = 0.f;
    h1[b][i] = hp[b] * W1[i] + b1[i];   // IN_DIM = 1
    __syncthreads();
    float a = b2[i];
#pragma unroll
    for (int k = 0; k < 32; k++) a += h1[b][k] * W2[i * 32 + k];
    g_h2[b * 32 + i] = a;
}

// ---------------- hypernet stage 2: w = tanh(h2 @ Wo^T + bo), + L1 reduce ----------------
__global__ void weightgen_kernel(const float* __restrict__ Wo, const float* __restrict__ bo,
                                 float* __restrict__ l1out)
{
    __shared__ float sh2[B * 32];
    __shared__ float wsum[8][B];
    int tid = threadIdx.x;
    sh2[tid] = g_h2[tid];
    __syncthreads();

    int j = blockIdx.x * 256 + tid;
    float s[B];
#pragma unroll
    for (int b = 0; b < B; b++) s[b] = 0.f;

    if (j < OUTD) {
        float wr[32];
        const float* row = Wo + (size_t)j * 32;
#pragma unroll
        for (int i = 0; i < 32; i++) wr[i] = row[i];
        float bj = bo[j];
#pragma unroll
        for (int b = 0; b < B; b++) {
            float a = bj;
#pragma unroll
            for (int i = 0; i < 32; i++) a += wr[i] * sh2[b * 32 + i];
            float w = tanhf(a);
            g_w[(size_t)b * OUTD + j] = w;
            s[b] = fabsf(w);
        }
    }
    int warp = tid >> 5, lane = tid & 31;
#pragma unroll
    for (int b = 0; b < B; b++) {
        float v = s[b];
        for (int off = 16; off > 0; off >>= 1) v += __shfl_xor_sync(0xFFFFFFFFu, v, off);
        if (lane == 0) wsum[warp][b] = v;
    }
    __syncthreads();
    if (tid < B) {
        float a = 0.f;
#pragma unroll
        for (int w = 0; w < 8; w++) a += wsum[w][tid];
        atomicAdd(&l1out[tid], a);
    }
}

// ---------------- 3x3 conv, pad=1, per-sample weights, software-pipelined ----------------
// Block: 256 threads, 32x32 spatial tile, OCB output channels.
// Each thread: 2x2 pixels x OCB oc; oc paired into f32x2 accumulators.
// NHWC=true: input is zf in [B,H,W,2] layout (layer 0, fuses the transpose).
template<int CIN, int OCB, bool NHWC>
__global__ __launch_bounds__(256, 2) void conv3x3_kernel(
    const float* __restrict__ in, float* __restrict__ out,
    const float* __restrict__ wbuf, int woff, int boff, int H, int relu)
{
    constexpr int CS   = (CIN < 4) ? CIN : 4;
    constexpr int OCP  = OCB / 2;
    constexpr int NIN  = (CS * 1156 + 255) / 256;
    constexpr int NWT  = (CS * OCP * 9 + 255) / 256;

    __shared__ float  sIn[CS * 1156];
    __shared__ float2 sW[CS * OCP * 9];

    int b   = blockIdx.z;
    int OC0 = blockIdx.y * OCB;
    int tiles = H >> 5;
    int ty0 = (blockIdx.x / tiles) << 5;
    int tx0 = (blockIdx.x % tiles) << 5;
    int tid = threadIdx.x;
    int tx = tid & 15, ty = tid >> 4;

    const float* wb  = wbuf + (size_t)b * OUTD;
    const float* inb = NHWC ? (in + (size_t)b * H * H * CIN)
                            : (in + (size_t)b * CIN * H * H);

    float  rIn[NIN];
    float2 rW[NWT];

    auto load_group = [&](int c0) {
#pragma unroll
        for (int i = 0; i < NIN; i++) {
            int idx = tid + i * 256;
            float v = 0.f;
            if (idx < CS * 1156) {
                int cs = idx / 1156, rem = idx - cs * 1156;
                int r = rem / 34, cc = rem - r * 34;
                int gy = ty0 - 1 + r, gx = tx0 - 1 + cc;
                if ((unsigned)gy < (unsigned)H && (unsigned)gx < (unsigned)H)
                    v = NHWC ? inb[((size_t)gy * H + gx) * CIN + (c0 + cs)]
                             : inb[(size_t)(c0 + cs) * H * H + gy * H + gx];
            }
            rIn[i] = v;
        }
#pragma unroll
        for (int i = 0; i < NWT; i++) {
            int idx = tid + i * 256;
            if (idx < CS * OCP * 9) {
                int cs = idx / (OCP * 9), rem = idx - cs * (OCP * 9);
                int ocp = rem / 9, k = rem - ocp * 9;
                const float* wp = wb + woff + ((size_t)(OC0 + 2 * ocp) * CIN + (c0 + cs)) * 9 + k;
                rW[i] = make_float2(wp[0], wp[CIN * 9]);
            }
        }
    };

    unsigned long long acc[OCP][4];
#pragma unroll
    for (int i = 0; i < OCP; i++)
#pragma unroll
        for (int p = 0; p < 4; p++) acc[i][p] = 0ull;

    load_group(0);

    for (int c0 = 0; c0 < CIN; c0 += CS) {
        __syncthreads();
#pragma unroll
        for (int i = 0; i < NIN; i++) {
            int idx = tid + i * 256;
            if (idx < CS * 1156) sIn[idx] = rIn[i];
        }
#pragma unroll
        for (int i = 0; i < NWT; i++) {
            int idx = tid + i * 256;
            if (idx < CS * OCP * 9) sW[idx] = rW[i];
        }
        __syncthreads();
        if (c0 + CS < CIN) load_group(c0 + CS);   // LDGs overlap the compute below

#pragma unroll
        for (int cs = 0; cs < CS; cs++) {
            float xi[16];
#pragma unroll
            for (int r = 0; r < 4; r++)
#pragma unroll
                for (int cc = 0; cc < 4; cc++)
                    xi[r * 4 + cc] = sIn[cs * 1156 + (2 * ty + r) * 34 + 2 * tx + cc];
#pragma unroll
            for (int ky = 0; ky < 3; ky++)
#pragma unroll
                for (int kx = 0; kx < 3; kx++) {
                    unsigned long long xx[4];
#pragma unroll
                    for (int py = 0; py < 2; py++)
#pragma unroll
                        for (int px = 0; px < 2; px++)
                            xx[py * 2 + px] = pack2b(xi[(py + ky) * 4 + (px + kx)]);
#pragma unroll
                    for (int ocp = 0; ocp < OCP; ocp++) {
                        unsigned long long w = *reinterpret_cast<const unsigned long long*>(
                            &sW[cs * OCP * 9 + ocp * 9 + ky * 3 + kx]);
#pragma unroll
                        for (int p = 0; p < 4; p++) fma2(acc[ocp][p], xx[p], w);
                    }
                }
        }
    }

    // epilogue: bias + relu + store
#pragma unroll
    for (int ocp = 0; ocp < OCP; ocp++) {
        float b0 = wb[boff + OC0 + 2 * ocp];
        float b1 = wb[boff + OC0 + 2 * ocp + 1];
        float* o0 = out + (((size_t)b * 64 + OC0 + 2 * ocp) * H) * H;
        float* o1 = o0 + (size_t)H * H;
#pragma unroll
        for (int py = 0; py < 2; py++)
#pragma unroll
            for (int px = 0; px < 2; px++) {
                float2 v = unpack2(acc[ocp][py * 2 + px]);
                v.x += b0; v.y += b1;
                if (relu) { v.x = fmaxf(v.x, 0.f); v.y = fmaxf(v.y, 0.f); }
                int y = ty0 + 2 * ty + py, x = tx0 + 2 * tx + px;
                o0[y * H + x] = v.x;
                o1[y * H + x] = v.y;
            }
    }
}

// ---------------- 2x2 maxpool ----------------
__global__ void maxpool_kernel(const float* __restrict__ in, float* __restrict__ out, int H, int W)
{
    int Ho = H >> 1, Wo = W >> 1;
    int total = B * 64 * Ho * Wo;
    int idx = blockIdx.x * blockDim.x + threadIdx.x;
    if (idx >= total) return;
    int xo = idx % Wo;
    int yo = (idx / Wo) % Ho;
    int bc = idx / (Wo * Ho);
    const float* p = in + (size_t)bc * H * W + (yo * 2) * W + xo * 2;
    float v = fmaxf(fmaxf(p[0], p[1]), fmaxf(p[W], p[W + 1]));
    out[idx] = v;
}

// ---------------- fused bilinear upsample x2 (ch 0..63) + skip copy (ch 64..127) ----------------
__global__ void up_concat_kernel(const float* __restrict__ in, const float* __restrict__ skip,
                                 float* __restrict__ out, int H, int W)
{
    int Ho = H * 2, Wo = W * 2;
    int total = B * 64 * Ho * Wo;
    int idx = blockIdx.x * blockDim.x + threadIdx.x;
    if (idx >= total) return;
    int xo = idx % Wo;
    int yo = (idx / Wo) % Ho;
    int c  = (idx / (Wo * Ho)) % 64;
    int b  = idx / (Wo * Ho * 64);

    float ys = (float)yo * (float)(H - 1) / (float)(Ho - 1);
    float xs = (float)xo * (float)(W - 1) / (float)(Wo - 1);
    int y0 = (int)floorf(ys); int y1 = min(y0 + 1, H - 1);
    int x0 = (int)floorf(xs); int x1 = min(x0 + 1, W - 1);
    float wy = ys - (float)y0, wx = xs - (float)x0;

    const float* p = in + ((size_t)b * 64 + c) * H * W;
    float r0 = p[y0 * W + x0] * (1.f - wy) + p[y1 * W + x0] * wy;
    float r1 = p[y0 * W + x1] * (1.f - wy) + p[y1 * W + x1] * wy;
    float v = r0 * (1.f - wx) + r1 * wx;

    size_t obase = (((size_t)b * 128 + c) * Ho + yo) * Wo + xo;
    out[obase] = v;
    out[obase + (size_t)64 * Ho * Wo] =
        skip[(((size_t)b * 64 + c) * Ho + yo) * Wo + xo];
}

// ---------------- final 1x1 conv (64->2) + residual + NCHW->NHWC ----------------
__global__ void final_kernel(const float* __restrict__ in, const float* __restrict__ zf,
                             const float* __restrict__ wbuf, int woff, int boff,
                             float* __restrict__ out)
{
    __shared__ float sw[130];
    int b  = blockIdx.y;
    int tid = threadIdx.x;
    const float* wb = wbuf + (size_t)b * OUTD;
    if (tid < 128) sw[tid] = wb[woff + tid];
    else if (tid < 130) sw[tid] = wb[boff + (tid - 128)];
    __syncthreads();
    int hw = blockIdx.x * 256 + tid;
    const float* inb = in + (size_t)b * 64 * 65536 + hw;
    float a0 = sw[128], a1 = sw[129];
#pragma unroll 8
    for (int c = 0; c < 64; c++) {
        float v = inb[(size_t)c * 65536];
        a0 = fmaf(v, sw[c], a0);
        a1 = fmaf(v, sw[64 + c], a1);
    }
    size_t o = ((size_t)b * 65536 + hw) * 2;
    out[o]     = zf[o]     + a0;
    out[o + 1] = zf[o + 1] + a1;
}

// ---------------- host side ----------------
static const int KOFF[15] = {0, 1152, 38016, 74880, 111744, 148608, 185472, 222336,
                             259200, 332928, 369792, 443520, 480384, 554112, 590976};
static const int CINL[15] = {2, 64, 64, 64, 64, 64, 64, 64, 128, 64, 128, 64, 128, 64, 64};
#define BOFF(i) (591104 + 64 * (i))

static inline void launch_conv(const float* in, float* out, const float* wb,
                               int layer, int H, int relu)
{
    int cin = CINL[layer];
    int tiles = (H / 32) * (H / 32);
    if (H <= 64) {
        // small layers: 8 oc per block for more blocks
        dim3 gs(tiles, 8, B);
        if (cin == 64)
            conv3x3_kernel<64, 8, false><<<gs, 256>>>(in, out, wb, KOFF[layer], BOFF(layer), H, relu);
        else
            conv3x3_kernel<128, 8, false><<<gs, 256>>>(in, out, wb, KOFF[layer], BOFF(layer), H, relu);
    } else {
        dim3 gs(tiles, 4, B);
        if (cin == 2)
            conv3x3_kernel<2, 16, true><<<gs, 256>>>(in, out, wb, KOFF[layer], BOFF(layer), H, relu);
        else if (cin == 64)
            conv3x3_kernel<64, 16, false><<<gs, 256>>>(in, out, wb, KOFF[layer], BOFF(layer), H, relu);
        else
            conv3x3_kernel<128, 16, false><<<gs, 256>>>(in, out, wb, KOFF[layer], BOFF(layer), H, relu);
    }
}

extern "C" void kernel_launch(void* const* d_in, const int* in_sizes, int n_in,
                              void* d_out, int out_size)
{
    const float* zf = (const float*)d_in[0];
    const float* hp = (const float*)d_in[2];
    const float* W1 = (const float*)d_in[3];
    const float* b1 = (const float*)d_in[4];
    const float* W2 = (const float*)d_in[5];
    const float* b2 = (const float*)d_in[6];
    const float* Wo = (const float*)d_in[7];
    const float* bo = (const float*)d_in[8];
    float* out = (float*)d_out;
    float* l1 = out + (size_t)B * 256 * 256 * 2;

    float *pA, *pB, *pS1, *pS2, *pS3, *pW;
    cudaGetSymbolAddress((void**)&pA,  g_bufA);
    cudaGetSymbolAddress((void**)&pB,  g_bufB);
    cudaGetSymbolAddress((void**)&pS1, g_skip1);
    cudaGetSymbolAddress((void**)&pS2, g_skip2);
    cudaGetSymbolAddress((void**)&pS3, g_skip3);
    cudaGetSymbolAddress((void**)&pW,  g_w);

    hyper1_kernel<<<1, 256>>>(hp, W1, b1, W2, b2, l1);
    weightgen_kernel<<<(OUTD + 255) / 256, 256>>>(Wo, bo, l1);

    // encoder (layer 0 reads zf NHWC directly)
    launch_conv(zf, pA, pW, 0, 256, 1);
    launch_conv(pA, pS1, pW, 1, 256, 1);
    { int n = B * 64 * 128 * 128; maxpool_kernel<<<(n + 255) / 256, 256>>>(pS1, pA, 256, 256); }
    launch_conv(pA, pB, pW, 2, 128, 1);
    launch_conv(pB, pS2, pW, 3, 128, 1);
    { int n = B * 64 * 64 * 64;   maxpool_kernel<<<(n + 255) / 256, 256>>>(pS2, pA, 128, 128); }
    launch_conv(pA, pB, pW, 4, 64, 1);
    launch_conv(pB, pS3, pW, 5, 64, 1);
    { int n = B * 64 * 32 * 32;   maxpool_kernel<<<(n + 255) / 256, 256>>>(pS3, pA, 64, 64); }
    launch_conv(pA, pB, pW, 6, 32, 1);
    launch_conv(pB, pA, pW, 7, 32, 1);

    // decoder level 1 (32 -> 64)
    { int n = B * 64 * 64 * 64;   up_concat_kernel<<<(n + 255) / 256, 256>>>(pA, pS3, pB, 32, 32); }
    launch_conv(pB, pA, pW, 8, 64, 1);
    launch_conv(pA, pB, pW, 9, 64, 1);

    // decoder level 2 (64 -> 128)
    { int n = B * 64 * 128 * 128; up_concat_kernel<<<(n + 255) / 256, 256>>>(pB, pS2, pA, 64, 64); }
    launch_conv(pA, pB, pW, 10, 128, 1);
    launch_conv(pB, pA, pW, 11, 128, 1);

    // decoder level 3 (128 -> 256)
    { int n = B * 64 * 256 * 256; up_concat_kernel<<<(n + 255) / 256, 256>>>(pA, pS1, pB, 128, 128); }
    launch_conv(pB, pA, pW, 12, 256, 1);
    launch_conv(pA, pB, pW, 13, 256, 1);

    {
        dim3 gs(65536 / 256, B);
        final_kernel<<<gs, 256>>>(pB, zf, pW, KOFF[14], BOFF(14), out);
    }
}

// round 5
// speedup vs baseline: 1.1595x; 1.0273x over previous
#include <cuda_runtime.h>
#include <math.h>
#include <stdint.h>

#define B 8
#define OUTD 592002
#define WPSTR 328320   // per-sample float2 count in g_wp

// ---------------- scratch (device globals; no allocation allowed) ----------------
__device__ float g_bufA[(size_t)B * 128 * 256 * 256];
__device__ float g_bufB[(size_t)B * 128 * 256 * 256];
__device__ float g_skip1[(size_t)B * 64 * 256 * 256];
__device__ float g_skip2[(size_t)B * 64 * 128 * 128];
__device__ float g_skip3[(size_t)B * 64 * 64 * 64];
__device__ float g_w[(size_t)B * OUTD];                    // flat generated weights
__device__ __align__(16) float2 g_wp[(size_t)B * WPSTR];   // paired conv weights
__device__ float g_h2[B * 32];

// ---------------- constant tables (static init; no memcpyToSymbol needed) ----------
__constant__ int cKOFF[14] = {0, 1152, 38016, 74880, 111744, 148608, 185472, 222336,
                              259200, 332928, 369792, 443520, 480384, 554112};
__constant__ int cCIN[14]  = {2, 64, 64, 64, 64, 64, 64, 64, 128, 64, 128, 64, 128, 64};
__constant__ int cWPOFF[14]= {0, 640, 21120, 41600, 62080, 82560, 103040, 123520,
                              144000, 184960, 205440, 246400, 266880, 307840};
__constant__ int cCUME[14] = {0, 576, 19008, 37440, 55872, 74304, 92736, 111168,
                              129600, 166464, 184896, 221760, 240192, 277056};

// ---------------- packed fp32 + cp.async helpers ----------------
__device__ __forceinline__ void fma2(unsigned long long& acc, unsigned long long x,
                                     unsigned long long w)
{
    asm("fma.rn.f32x2 %0, %1, %2, %0;" : "+l"(acc) : "l"(x), "l"(w));
}
__device__ __forceinline__ unsigned long long pack2b(float a)
{
    unsigned long long r;
    asm("mov.b64 %0, {%1, %1};" : "=l"(r) : "f"(a));
    return r;
}
__device__ __forceinline__ float2 unpack2(unsigned long long v)
{
    float2 r;
    asm("mov.b64 {%0, %1}, %2;" : "=f"(r.x), "=f"(r.y) : "l"(v));
    return r;
}
__device__ __forceinline__ void cp4(uint32_t dst, const void* src)
{
    asm volatile("cp.async.ca.shared.global [%0], [%1], 4;" :: "r"(dst), "l"(src) : "memory");
}
__device__ __forceinline__ void cp16(uint32_t dst, const void* src)
{
    asm volatile("cp.async.cg.shared.global [%0], [%1], 16;" :: "r"(dst), "l"(src) : "memory");
}
__device__ __forceinline__ void cp_commit()
{
    asm volatile("cp.async.commit_group;" ::: "memory");
}
__device__ __forceinline__ void cp_wait1()
{
    asm volatile("cp.async.wait_group 1;" ::: "memory");
}
__device__ __forceinline__ void cp_wait0()
{
    asm volatile("cp.async.wait_group 0;" ::: "memory");
}

// ---------------- hypernet stage 1 (+ zero l1) ----------------
__global__ void hyper1_kernel(const float* __restrict__ hp, const float* __restrict__ W1,
                              const float* __restrict__ b1, const float* __restrict__ W2,
                              const float* __restrict__ b2, float* __restrict__ l1)
{
    __shared__ float h1[B][32];
    int b = threadIdx.x >> 5;
    int i = threadIdx.x & 31;
    if (threadIdx.x < B) l1[threadIdx.x] = 0.f;
    h1[b][i] = hp[b] * W1[i] + b1[i];   // IN_DIM = 1
    __syncthreads();
    float a = b2[i];
#pragma unroll
    for (int k = 0; k < 32; k++) a += h1[b][k] * W2[i * 32 + k];
    g_h2[b * 32 + i] = a;
}

// ---------------- hypernet stage 2: w = tanh(h2 @ Wo^T + bo), + L1 reduce ----------------
__global__ void weightgen_kernel(const float* __restrict__ Wo, const float* __restrict__ bo,
                                 float* __restrict__ l1out)
{
    __shared__ float sh2[B * 32];
    __shared__ float wsum[8][B];
    int tid = threadIdx.x;
    sh2[tid] = g_h2[tid];
    __syncthreads();

    int j = blockIdx.x * 256 + tid;
    float s[B];
#pragma unroll
    for (int b = 0; b < B; b++) s[b] = 0.f;

    if (j < OUTD) {
        float wr[32];
        const float* row = Wo + (size_t)j * 32;
#pragma unroll
        for (int i = 0; i < 32; i++) wr[i] = row[i];
        float bj = bo[j];
#pragma unroll
        for (int b = 0; b < B; b++) {
            float a = bj;
#pragma unroll
            for (int i = 0; i < 32; i++) a += wr[i] * sh2[b * 32 + i];
            float w = tanhf(a);
            g_w[(size_t)b * OUTD + j] = w;
            s[b] = fabsf(w);
        }
    }
    int warp = tid >> 5, lane = tid & 31;
#pragma unroll
    for (int b = 0; b < B; b++) {
        float v = s[b];
        for (int off = 16; off > 0; off >>= 1) v += __shfl_xor_sync(0xFFFFFFFFu, v, off);
        if (lane == 0) wsum[warp][b] = v;
    }
    __syncthreads();
    if (tid < B) {
        float a = 0.f;
#pragma unroll
        for (int w = 0; w < 8; w++) a += wsum[w][tid];
        atomicAdd(&l1out[tid], a);
    }
}

// ---------------- repack conv weights into paired layout ----------------
// g_wp layout per (sample, layer): [(c*32 + ocp)*10 + k] float2 = (w[2ocp][c][k], w[2ocp+1][c][k])
__global__ void repack_kernel()
{
    const int PER = 295488;   // per-sample elements (c,ocp,k triples)
    int e = blockIdx.x * 256 + threadIdx.x;
    if (e >= B * PER) return;
    int b = e / PER;
    int r = e - b * PER;
    int l = 13;
#pragma unroll
    for (int i = 13; i > 0; i--)
        if (r < cCUME[i]) l = i - 1;
    int q = r - cCUME[l];
    int cin = cCIN[l];
    int c   = q / 288;
    int t   = q - c * 288;
    int ocp = t / 9;
    int k   = t - ocp * 9;
    const float* wb = g_w + (size_t)b * OUTD + cKOFF[l];
    float w0 = wb[((2 * ocp) * cin + c) * 9 + k];
    float w1 = wb[((2 * ocp + 1) * cin + c) * 9 + k];
    g_wp[(size_t)b * WPSTR + cWPOFF[l] + (c * 32 + ocp) * 10 + k] = make_float2(w0, w1);
}

// ---------------- 3x3 conv, pad=1, cp.async double-buffered, f32x2 ----------------
// Block: 256 threads, 32x32 spatial tile, OCB output channels; thread = 2x2 px x OCB oc.
template<int CIN, int OCB, bool NHWC>
__global__ __launch_bounds__(256, 2) void conv3x3_kernel(
    const float* __restrict__ in, float* __restrict__ out,
    const float2* __restrict__ wp, const float* __restrict__ wbuf,
    int wpoff, int boff, int H, int relu)
{
    constexpr int CS  = (CIN < 4) ? CIN : 4;
    constexpr int OCP = OCB / 2;
    constexpr int G   = CIN / CS;
    constexpr int INSZ = CS * 1156;          // floats per buffer
    constexpr int WCHK = CS * OCP * 5;       // 16B chunks per buffer

    __shared__ __align__(16) float  sIn[2 * INSZ];
    __shared__ __align__(16) float2 sW[2 * CS * OCP * 10];

    int b   = blockIdx.z;
    int op0 = blockIdx.y * OCP;              // global oc-pair start
    int tiles = H >> 5;
    int ty0 = (blockIdx.x / tiles) << 5;
    int tx0 = (blockIdx.x % tiles) << 5;
    int tid = threadIdx.x;
    int tx = tid & 15, ty = tid >> 4;

    const float* inb = NHWC ? (in + (size_t)b * H * H * CIN)
                            : (in + (size_t)b * CIN * H * H);
    const char* wpb = (const char*)(wp + (size_t)b * WPSTR + wpoff);
    uint32_t siAddr = (uint32_t)__cvta_generic_to_shared(sIn);
    uint32_t swAddr = (uint32_t)__cvta_generic_to_shared(sW);

    auto stage = [&](int g, int buf) {
        int c0 = g * CS;
        // input tile: CS channels of 34x34, zero halo
        for (int idx = tid; idx < INSZ; idx += 256) {
            int cs = idx / 1156, rem = idx - cs * 1156;
            int r = rem / 34, cc = rem - r * 34;
            int gy = ty0 - 1 + r, gx = tx0 - 1 + cc;
            uint32_t dst = siAddr + (buf * INSZ + idx) * 4;
            if ((unsigned)gy < (unsigned)H && (unsigned)gx < (unsigned)H) {
                const float* src = NHWC ? &inb[((size_t)gy * H + gx) * CIN + c0 + cs]
                                        : &inb[(size_t)(c0 + cs) * H * H + (size_t)gy * H + gx];
                cp4(dst, src);
            } else {
                sIn[buf * INSZ + idx] = 0.f;
            }
        }
        // weights: CS rows of OCP*10 float2, contiguous 16B chunks
        for (int idx = tid; idx < WCHK; idx += 256) {
            int cs = idx / (OCP * 5), rem = idx - cs * (OCP * 5);
            const char* src = wpb + ((size_t)(c0 + cs) * 32 + op0) * 80 + rem * 16;
            uint32_t dst = swAddr + (buf * CS * OCP * 10 + cs * OCP * 10) * 8 + rem * 16;
            cp16(dst, src);
        }
    };

    unsigned long long acc[OCP][4];
#pragma unroll
    for (int i = 0; i < OCP; i++)
#pragma unroll
        for (int p = 0; p < 4; p++) acc[i][p] = 0ull;

    stage(0, 0);
    cp_commit();

    for (int g = 0; g < G; g++) {
        if (g + 1 < G) { stage(g + 1, (g + 1) & 1); cp_commit(); cp_wait1(); }
        else           { cp_wait0(); }
        __syncthreads();

        const float*  sib = sIn + (g & 1) * INSZ;
        const float2* swb = sW + (g & 1) * CS * OCP * 10;
#pragma unroll
        for (int cs = 0; cs < CS; cs++) {
            const float* si = sib + cs * 1156 + (2 * ty) * 34 + 2 * tx;
            unsigned long long xp[16];
#pragma unroll
            for (int r = 0; r < 4; r++) {
                float2 a = *(const float2*)(si + r * 34);
                float2 c = *(const float2*)(si + r * 34 + 2);
                xp[r * 4 + 0] = pack2b(a.x);
                xp[r * 4 + 1] = pack2b(a.y);
                xp[r * 4 + 2] = pack2b(c.x);
                xp[r * 4 + 3] = pack2b(c.y);
            }
            const unsigned long long* wr64 =
                (const unsigned long long*)(swb + cs * OCP * 10);
#pragma unroll
            for (int ocp = 0; ocp < OCP; ocp++) {
#pragma unroll
                for (int ky = 0; ky < 3; ky++)
#pragma unroll
                    for (int kx = 0; kx < 3; kx++) {
                        unsigned long long w = wr64[ocp * 10 + ky * 3 + kx];
#pragma unroll
                        for (int py = 0; py < 2; py++)
#pragma unroll
                            for (int px = 0; px < 2; px++)
                                fma2(acc[ocp][py * 2 + px],
                                     xp[(py + ky) * 4 + px + kx], w);
                    }
            }
        }
        __syncthreads();
    }

    // epilogue: bias + relu + store (NCHW)
    const float* wb = wbuf + (size_t)b * OUTD;
#pragma unroll
    for (int ocp = 0; ocp < OCP; ocp++) {
        int oc = 2 * (op0 + ocp);
        float b0 = wb[boff + oc];
        float b1 = wb[boff + oc + 1];
        float* o0 = out + (((size_t)b * 64 + oc) * H) * H;
        float* o1 = o0 + (size_t)H * H;
#pragma unroll
        for (int py = 0; py < 2; py++)
#pragma unroll
            for (int px = 0; px < 2; px++) {
                float2 v = unpack2(acc[ocp][py * 2 + px]);
                v.x += b0; v.y += b1;
                if (relu) { v.x = fmaxf(v.x, 0.f); v.y = fmaxf(v.y, 0.f); }
                int y = ty0 + 2 * ty + py, x = tx0 + 2 * tx + px;
                o0[y * H + x] = v.x;
                o1[y * H + x] = v.y;
            }
    }
}

// ---------------- 2x2 maxpool ----------------
__global__ void maxpool_kernel(const float* __restrict__ in, float* __restrict__ out, int H, int W)
{
    int Ho = H >> 1, Wo = W >> 1;
    int total = B * 64 * Ho * Wo;
    int idx = blockIdx.x * blockDim.x + threadIdx.x;
    if (idx >= total) return;
    int xo = idx % Wo;
    int yo = (idx / Wo) % Ho;
    int bc = idx / (Wo * Ho);
    const float* p = in + (size_t)bc * H * W + (yo * 2) * W + xo * 2;
    float v = fmaxf(fmaxf(p[0], p[1]), fmaxf(p[W], p[W + 1]));
    out[idx] = v;
}

// ---------------- fused bilinear upsample x2 + skip copy ----------------
__global__ void up_concat_kernel(const float* __restrict__ in, const float* __restrict__ skip,
                                 float* __restrict__ out, int H, int W)
{
    int Ho = H * 2, Wo = W * 2;
    int total = B * 64 * Ho * Wo;
    int idx = blockIdx.x * blockDim.x + threadIdx.x;
    if (idx >= total) return;
    int xo = idx % Wo;
    int yo = (idx / Wo) % Ho;
    int c  = (idx / (Wo * Ho)) % 64;
    int b  = idx / (Wo * Ho * 64);

    float ys = (float)yo * (float)(H - 1) / (float)(Ho - 1);
    float xs = (float)xo * (float)(W - 1) / (float)(Wo - 1);
    int y0 = (int)floorf(ys); int y1 = min(y0 + 1, H - 1);
    int x0 = (int)floorf(xs); int x1 = min(x0 + 1, W - 1);
    float wy = ys - (float)y0, wx = xs - (float)x0;

    const float* p = in + ((size_t)b * 64 + c) * H * W;
    float r0 = p[y0 * W + x0] * (1.f - wy) + p[y1 * W + x0] * wy;
    float r1 = p[y0 * W + x1] * (1.f - wy) + p[y1 * W + x1] * wy;
    float v = r0 * (1.f - wx) + r1 * wx;

    size_t obase = (((size_t)b * 128 + c) * Ho + yo) * Wo + xo;
    out[obase] = v;
    out[obase + (size_t)64 * Ho * Wo] =
        skip[(((size_t)b * 64 + c) * Ho + yo) * Wo + xo];
}

// ---------------- final 1x1 conv (64->2) + residual + NCHW->NHWC ----------------
__global__ void final_kernel(const float* __restrict__ in, const float* __restrict__ zf,
                             const float* __restrict__ wbuf, int woff, int boff,
                             float* __restrict__ out)
{
    __shared__ float sw[130];
    int b  = blockIdx.y;
    int tid = threadIdx.x;
    const float* wb = wbuf + (size_t)b * OUTD;
    if (tid < 128) sw[tid] = wb[woff + tid];
    else if (tid < 130) sw[tid] = wb[boff + (tid - 128)];
    __syncthreads();
    int hw = blockIdx.x * 256 + tid;
    const float* inb = in + (size_t)b * 64 * 65536 + hw;
    float a0 = sw[128], a1 = sw[129];
#pragma unroll 8
    for (int c = 0; c < 64; c++) {
        float v = inb[(size_t)c * 65536];
        a0 = fmaf(v, sw[c], a0);
        a1 = fmaf(v, sw[64 + c], a1);
    }
    size_t o = ((size_t)b * 65536 + hw) * 2;
    out[o]     = zf[o]     + a0;
    out[o + 1] = zf[o + 1] + a1;
}

// ---------------- host side ----------------
static const int KOFF[15] = {0, 1152, 38016, 74880, 111744, 148608, 185472, 222336,
                             259200, 332928, 369792, 443520, 480384, 554112, 590976};
static const int CINL[15] = {2, 64, 64, 64, 64, 64, 64, 64, 128, 64, 128, 64, 128, 64, 64};
static const int WPOFF[14]= {0, 640, 21120, 41600, 62080, 82560, 103040, 123520,
                             144000, 184960, 205440, 246400, 266880, 307840};
#define BOFF(i) (591104 + 64 * (i))

static inline void launch_conv(const float* in, float* out, const float2* wp,
                               const float* wb, int layer, int H, int relu)
{
    int cin = CINL[layer];
    int tiles = (H / 32) * (H / 32);
    if (H <= 64) {
        dim3 gs(tiles, 8, B);   // OCB=8 -> 8 oc groups
        if (cin == 64)
            conv3x3_kernel<64, 8, false><<<gs, 256>>>(in, out, wp, wb, WPOFF[layer], BOFF(layer), H, relu);
        else
            conv3x3_kernel<128, 8, false><<<gs, 256>>>(in, out, wp, wb, WPOFF[layer], BOFF(layer), H, relu);
    } else {
        dim3 gs(tiles, 4, B);   // OCB=16
        if (cin == 2)
            conv3x3_kernel<2, 16, true><<<gs, 256>>>(in, out, wp, wb, WPOFF[layer], BOFF(layer), H, relu);
        else if (cin == 64)
            conv3x3_kernel<64, 16, false><<<gs, 256>>>(in, out, wp, wb, WPOFF[layer], BOFF(layer), H, relu);
        else
            conv3x3_kernel<128, 16, false><<<gs, 256>>>(in, out, wp, wb, WPOFF[layer], BOFF(layer), H, relu);
    }
}

extern "C" void kernel_launch(void* const* d_in, const int* in_sizes, int n_in,
                              void* d_out, int out_size)
{
    const float* zf = (const float*)d_in[0];
    const float* hp = (const float*)d_in[2];
    const float* W1 = (const float*)d_in[3];
    const float* b1 = (const float*)d_in[4];
    const float* W2 = (const float*)d_in[5];
    const float* b2 = (const float*)d_in[6];
    const float* Wo = (const float*)d_in[7];
    const float* bo = (const float*)d_in[8];
    float* out = (float*)d_out;
    float* l1 = out + (size_t)B * 256 * 256 * 2;

    float *pA, *pB, *pS1, *pS2, *pS3, *pW;
    float2* pWP;
    cudaGetSymbolAddress((void**)&pA,  g_bufA);
    cudaGetSymbolAddress((void**)&pB,  g_bufB);
    cudaGetSymbolAddress((void**)&pS1, g_skip1);
    cudaGetSymbolAddress((void**)&pS2, g_skip2);
    cudaGetSymbolAddress((void**)&pS3, g_skip3);
    cudaGetSymbolAddress((void**)&pW,  g_w);
    cudaGetSymbolAddress((void**)&pWP, g_wp);

    hyper1_kernel<<<1, 256>>>(hp, W1, b1, W2, b2, l1);
    weightgen_kernel<<<(OUTD + 255) / 256, 256>>>(Wo, bo, l1);
    repack_kernel<<<(B * 295488 + 255) / 256, 256>>>();

    // encoder (layer 0 reads zf NHWC directly)
    launch_conv(zf, pA, pWP, pW, 0, 256, 1);
    launch_conv(pA, pS1, pWP, pW, 1, 256, 1);
    { int n = B * 64 * 128 * 128; maxpool_kernel<<<(n + 255) / 256, 256>>>(pS1, pA, 256, 256); }
    launch_conv(pA, pB, pWP, pW, 2, 128, 1);
    launch_conv(pB, pS2, pWP, pW, 3, 128, 1);
    { int n = B * 64 * 64 * 64;   maxpool_kernel<<<(n + 255) / 256, 256>>>(pS2, pA, 128, 128); }
    launch_conv(pA, pB, pWP, pW, 4, 64, 1);
    launch_conv(pB, pS3, pWP, pW, 5, 64, 1);
    { int n = B * 64 * 32 * 32;   maxpool_kernel<<<(n + 255) / 256, 256>>>(pS3, pA, 64, 64); }
    launch_conv(pA, pB, pWP, pW, 6, 32, 1);
    launch_conv(pB, pA, pWP, pW, 7, 32, 1);

    // decoder level 1 (32 -> 64)
    { int n = B * 64 * 64 * 64;   up_concat_kernel<<<(n + 255) / 256, 256>>>(pA, pS3, pB, 32, 32); }
    launch_conv(pB, pA, pWP, pW, 8, 64, 1);
    launch_conv(pA, pB, pWP, pW, 9, 64, 1);

    // decoder level 2 (64 -> 128)
    { int n = B * 64 * 128 * 128; up_concat_kernel<<<(n + 255) / 256, 256>>>(pB, pS2, pA, 64, 64); }
    launch_conv(pA, pB, pWP, pW, 10, 128, 1);
    launch_conv(pB, pA, pWP, pW, 11, 128, 1);

    // decoder level 3 (128 -> 256)
    { int n = B * 64 * 256 * 256; up_concat_kernel<<<(n + 255) / 256, 256>>>(pA, pS1, pB, 128, 128); }
    launch_conv(pB, pA, pWP, pW, 12, 256, 1);
    launch_conv(pA, pB, pWP, pW, 13, 256, 1);

    {
        dim3 gs(65536 / 256, B);
        final_kernel<<<gs, 256>>>(pB, zf, pW, KOFF[14], BOFF(14), out);
    }
}

// round 6
// speedup vs baseline: 1.2873x; 1.1102x over previous
#include <cuda_runtime.h>
#include <math.h>
#include <stdint.h>

#define B 8
#define OUTD 592002
#define WPSTR 328320   // per-sample float2 count in g_wp

// ---------------- scratch (device globals; no allocation allowed) ----------------
__device__ float g_bufA[(size_t)B * 128 * 256 * 256];
__device__ float g_bufB[(size_t)B * 128 * 256 * 256];
__device__ float g_skip1[(size_t)B * 64 * 256 * 256];
__device__ float g_skip2[(size_t)B * 64 * 128 * 128];
__device__ float g_skip3[(size_t)B * 64 * 64 * 64];
__device__ float g_w[(size_t)B * OUTD];                    // flat generated weights
__device__ __align__(16) float2 g_wp[(size_t)B * WPSTR];   // paired conv weights
__device__ float g_h2[B * 32];

// ---------------- constant tables ----------------
__constant__ int cKOFF[14] = {0, 1152, 38016, 74880, 111744, 148608, 185472, 222336,
                              259200, 332928, 369792, 443520, 480384, 554112};
__constant__ int cCIN[14]  = {2, 64, 64, 64, 64, 64, 64, 64, 128, 64, 128, 64, 128, 64};
__constant__ int cWPOFF[14]= {0, 640, 21120, 41600, 62080, 82560, 103040, 123520,
                              144000, 184960, 205440, 246400, 266880, 307840};
__constant__ int cCUME[14] = {0, 576, 19008, 37440, 55872, 74304, 92736, 111168,
                              129600, 166464, 184896, 221760, 240192, 277056};

// ---------------- packed fp32 + cp.async helpers ----------------
__device__ __forceinline__ void fma2(unsigned long long& acc, unsigned long long x,
                                     unsigned long long w)
{
    asm("fma.rn.f32x2 %0, %1, %2, %0;" : "+l"(acc) : "l"(x), "l"(w));
}
__device__ __forceinline__ unsigned long long pack2b(float a)
{
    unsigned long long r;
    asm("mov.b64 %0, {%1, %1};" : "=l"(r) : "f"(a));
    return r;
}
__device__ __forceinline__ float2 unpack2(unsigned long long v)
{
    float2 r;
    asm("mov.b64 {%0, %1}, %2;" : "=f"(r.x), "=f"(r.y) : "l"(v));
    return r;
}
__device__ __forceinline__ void cp4(uint32_t dst, const void* src)
{
    asm volatile("cp.async.ca.shared.global [%0], [%1], 4;" :: "r"(dst), "l"(src) : "memory");
}
__device__ __forceinline__ void cp16(uint32_t dst, const void* src)
{
    asm volatile("cp.async.cg.shared.global [%0], [%1], 16;" :: "r"(dst), "l"(src) : "memory");
}
__device__ __forceinline__ void cp16z(uint32_t dst, const void* src, int sz)
{
    // src_size variant: if sz==0, 16 bytes of zeros are written, nothing is read
    asm volatile("cp.async.cg.shared.global [%0], [%1], 16, %2;"
                 :: "r"(dst), "l"(src), "r"(sz) : "memory");
}
__device__ __forceinline__ void cp_commit()
{
    asm volatile("cp.async.commit_group;" ::: "memory");
}
__device__ __forceinline__ void cp_wait1()
{
    asm volatile("cp.async.wait_group 1;" ::: "memory");
}
__device__ __forceinline__ void cp_wait0()
{
    asm volatile("cp.async.wait_group 0;" ::: "memory");
}

// ---------------- hypernet stage 1 (+ zero l1) ----------------
__global__ void hyper1_kernel(const float* __restrict__ hp, const float* __restrict__ W1,
                              const float* __restrict__ b1, const float* __restrict__ W2,
                              const float* __restrict__ b2, float* __restrict__ l1)
{
    __shared__ float h1[B][32];
    int b = threadIdx.x >> 5;
    int i = threadIdx.x & 31;
    if (threadIdx.x < B) l1[threadIdx.x] = 0.f;
    h1[b][i] = hp[b] * W1[i] + b1[i];   // IN_DIM = 1
    __syncthreads();
    float a = b2[i];
#pragma unroll
    for (int k = 0; k < 32; k++) a += h1[b][k] * W2[i * 32 + k];
    g_h2[b * 32 + i] = a;
}

// ---------------- hypernet stage 2 ----------------
__global__ void weightgen_kernel(const float* __restrict__ Wo, const float* __restrict__ bo,
                                 float* __restrict__ l1out)
{
    __shared__ float sh2[B * 32];
    __shared__ float wsum[8][B];
    int tid = threadIdx.x;
    sh2[tid] = g_h2[tid];
    __syncthreads();

    int j = blockIdx.x * 256 + tid;
    float s[B];
#pragma unroll
    for (int b = 0; b < B; b++) s[b] = 0.f;

    if (j < OUTD) {
        float wr[32];
        const float* row = Wo + (size_t)j * 32;
#pragma unroll
        for (int i = 0; i < 32; i++) wr[i] = row[i];
        float bj = bo[j];
#pragma unroll
        for (int b = 0; b < B; b++) {
            float a = bj;
#pragma unroll
            for (int i = 0; i < 32; i++) a += wr[i] * sh2[b * 32 + i];
            float w = tanhf(a);
            g_w[(size_t)b * OUTD + j] = w;
            s[b] = fabsf(w);
        }
    }
    int warp = tid >> 5, lane = tid & 31;
#pragma unroll
    for (int b = 0; b < B; b++) {
        float v = s[b];
        for (int off = 16; off > 0; off >>= 1) v += __shfl_xor_sync(0xFFFFFFFFu, v, off);
        if (lane == 0) wsum[warp][b] = v;
    }
    __syncthreads();
    if (tid < B) {
        float a = 0.f;
#pragma unroll
        for (int w = 0; w < 8; w++) a += wsum[w][tid];
        atomicAdd(&l1out[tid], a);
    }
}

// ---------------- repack conv weights into paired layout ----------------
// per (sample, layer): [(c*32 + ocp)*10 + k] float2 = (w[2ocp][c][k], w[2ocp+1][c][k])
__global__ void repack_kernel()
{
    const int PER = 295488;
    int e = blockIdx.x * 256 + threadIdx.x;
    if (e >= B * PER) return;
    int b = e / PER;
    int r = e - b * PER;
    int l = 13;
#pragma unroll
    for (int i = 13; i > 0; i--)
        if (r < cCUME[i]) l = i - 1;
    int q = r - cCUME[l];
    int cin = cCIN[l];
    int c   = q / 288;
    int t   = q - c * 288;
    int ocp = t / 9;
    int k   = t - ocp * 9;
    const float* wb = g_w + (size_t)b * OUTD + cKOFF[l];
    float w0 = wb[((2 * ocp) * cin + c) * 9 + k];
    float w1 = wb[((2 * ocp + 1) * cin + c) * 9 + k];
    float2* dst = &g_wp[(size_t)b * WPSTR + cWPOFF[l] + (c * 32 + ocp) * 10 + k];
    *dst = make_float2(w0, w1);
    if (k == 0) dst[9] = make_float2(0.f, 0.f);   // pad slot
}

// ---------------- 3x3 conv: cp16 staging, LDS.128 weights, f32x2 math ----------------
// Block: 256 threads, 32x32 tile, OCB oc. Thread: 2x2 px x OCB oc (oc-paired f32x2).
// smem input rows are 40 wide: col c <-> gx = tx0-4+c.
template<int CIN, int OCB, bool NHWC>
__global__ __launch_bounds__(256, 2) void conv3x3_kernel(
    const float* __restrict__ in, float* __restrict__ out,
    const float2* __restrict__ wp, const float* __restrict__ wbuf,
    int wpoff, int boff, int H, int relu)
{
    constexpr int CS   = (CIN < 4) ? CIN : 4;
    constexpr int OCP  = OCB / 2;
    constexpr int G    = CIN / CS;
    constexpr int CROW = 34 * 40;          // floats per channel tile
    constexpr int INSZ = CS * CROW;        // floats per buffer
    constexpr int WPC  = OCP * 10;         // float2 per channel (weights)
    constexpr int WCHK = CS * OCP * 5;     // 16B chunks per buffer

    __shared__ __align__(16) float  sIn[2 * INSZ];
    __shared__ __align__(16) float2 sW[2 * CS * WPC];

    int b   = blockIdx.z;
    int op0 = blockIdx.y * OCP;
    int tiles = H >> 5;
    int ty0 = (blockIdx.x / tiles) << 5;
    int tx0 = (blockIdx.x % tiles) << 5;
    int tid = threadIdx.x;
    int tx = tid & 15, ty = tid >> 4;

    const float* inb = NHWC ? (in + (size_t)b * H * H * CIN)
                            : (in + (size_t)b * CIN * H * H);
    const char* wpb = (const char*)(wp + (size_t)b * WPSTR + wpoff);
    uint32_t siAddr = (uint32_t)__cvta_generic_to_shared(sIn);
    uint32_t swAddr = (uint32_t)__cvta_generic_to_shared(sW);

    auto stage = [&](int g, int buf) {
        int c0 = g * CS;
        if (NHWC) {
            // per-element cp4 (layer 0 only, CIN=2)
            for (int idx = tid; idx < CS * 1156; idx += 256) {
                int cs = idx / 1156, rem = idx - cs * 1156;
                int r = rem / 34, cc = rem - r * 34;
                int gy = ty0 - 1 + r, gx = tx0 - 1 + cc;
                int soff = buf * INSZ + cs * CROW + r * 40 + cc + 3;
                if ((unsigned)gy < (unsigned)H && (unsigned)gx < (unsigned)H)
                    cp4(siAddr + soff * 4, &inb[((size_t)gy * H + gx) * CIN + c0 + cs]);
                else
                    sIn[soff] = 0.f;
            }
        } else {
            // 16B chunks, zero-fill OOB via src_size=0
            for (int idx = tid; idx < CS * 340; idx += 256) {
                int cs = idx / 340, rem = idx - cs * 340;
                int r = rem / 10, j = rem - r * 10;
                int gy = ty0 - 1 + r;
                int gxb = tx0 - 4 + 4 * j;
                bool ok = ((unsigned)gy < (unsigned)H) && ((unsigned)gxb < (unsigned)H);
                const float* src = ok ? &inb[(size_t)(c0 + cs) * H * H + (size_t)gy * H + gxb]
                                      : inb;
                cp16z(siAddr + (buf * INSZ + cs * CROW + r * 40 + 4 * j) * 4, src, ok ? 16 : 0);
            }
        }
        // weights: contiguous 16B chunks
        for (int idx = tid; idx < WCHK; idx += 256) {
            int cs = idx / (OCP * 5), rem = idx - cs * (OCP * 5);
            const char* src = wpb + ((size_t)(c0 + cs) * 32 + op0) * 80 + rem * 16;
            uint32_t dst = swAddr + (buf * CS * WPC + cs * WPC) * 8 + rem * 16;
            cp16(dst, src);
        }
    };

    unsigned long long acc[OCP][4];
#pragma unroll
    for (int i = 0; i < OCP; i++)
#pragma unroll
        for (int p = 0; p < 4; p++) acc[i][p] = 0ull;

    stage(0, 0);
    cp_commit();

    for (int g = 0; g < G; g++) {
        if (g + 1 < G) { stage(g + 1, (g + 1) & 1); cp_commit(); cp_wait1(); }
        else           { cp_wait0(); }
        __syncthreads();

        const float*  sib = sIn + (g & 1) * INSZ;
        const float2* swb = sW + (g & 1) * CS * WPC;

#pragma unroll
        for (int cs = 0; cs < CS; cs++) {
            const float* si = sib + cs * CROW + (2 * ty) * 40 + 2 * tx + 3;
            unsigned long long xp[16];
#pragma unroll
            for (int r = 0; r < 4; r++) {
                float a0 = si[r * 40];
                float2 am = *(const float2*)(si + r * 40 + 1);
                float a3 = si[r * 40 + 3];
                xp[r * 4 + 0] = pack2b(a0);
                xp[r * 4 + 1] = pack2b(am.x);
                xp[r * 4 + 2] = pack2b(am.y);
                xp[r * 4 + 3] = pack2b(a3);
            }
            const ulonglong2* wq = (const ulonglong2*)(swb + cs * WPC);
            const unsigned long long* wq1 = (const unsigned long long*)wq;

#define TAP(o, ky, kx, w) \
            fma2(acc[o][0], xp[(0 + ky) * 4 + 0 + kx], (w)); \
            fma2(acc[o][1], xp[(0 + ky) * 4 + 1 + kx], (w)); \
            fma2(acc[o][2], xp[(1 + ky) * 4 + 0 + kx], (w)); \
            fma2(acc[o][3], xp[(1 + ky) * 4 + 1 + kx], (w));

#pragma unroll
            for (int ocp = 0; ocp < OCP; ocp++) {
                ulonglong2 wA = wq[ocp * 5 + 0];
                TAP(ocp, 0, 0, wA.x); TAP(ocp, 0, 1, wA.y);
                ulonglong2 wB = wq[ocp * 5 + 1];
                TAP(ocp, 0, 2, wB.x); TAP(ocp, 1, 0, wB.y);
                ulonglong2 wC = wq[ocp * 5 + 2];
                TAP(ocp, 1, 1, wC.x); TAP(ocp, 1, 2, wC.y);
                ulonglong2 wD = wq[ocp * 5 + 3];
                TAP(ocp, 2, 0, wD.x); TAP(ocp, 2, 1, wD.y);
                unsigned long long wE = wq1[ocp * 10 + 8];
                TAP(ocp, 2, 2, wE);
            }
#undef TAP
        }
        __syncthreads();
    }

    // epilogue: bias + relu + store (NCHW)
    const float* wb = wbuf + (size_t)b * OUTD;
#pragma unroll
    for (int ocp = 0; ocp < OCP; ocp++) {
        int oc = 2 * (op0 + ocp);
        float b0 = wb[boff + oc];
        float b1 = wb[boff + oc + 1];
        float* o0 = out + (((size_t)b * 64 + oc) * H) * H;
        float* o1 = o0 + (size_t)H * H;
#pragma unroll
        for (int py = 0; py < 2; py++)
#pragma unroll
            for (int px = 0; px < 2; px++) {
                float2 v = unpack2(acc[ocp][py * 2 + px]);
                v.x += b0; v.y += b1;
                if (relu) { v.x = fmaxf(v.x, 0.f); v.y = fmaxf(v.y, 0.f); }
                int y = ty0 + 2 * ty + py, x = tx0 + 2 * tx + px;
                o0[y * H + x] = v.x;
                o1[y * H + x] = v.y;
            }
    }
}

// ---------------- 2x2 maxpool ----------------
__global__ void maxpool_kernel(const float* __restrict__ in, float* __restrict__ out, int H, int W)
{
    int Ho = H >> 1, Wo = W >> 1;
    int total = B * 64 * Ho * Wo;
    int idx = blockIdx.x * blockDim.x + threadIdx.x;
    if (idx >= total) return;
    int xo = idx % Wo;
    int yo = (idx / Wo) % Ho;
    int bc = idx / (Wo * Ho);
    const float* p = in + (size_t)bc * H * W + (yo * 2) * W + xo * 2;
    float v = fmaxf(fmaxf(p[0], p[1]), fmaxf(p[W], p[W + 1]));
    out[idx] = v;
}

// ---------------- fused bilinear upsample x2 + skip copy ----------------
__global__ void up_concat_kernel(const float* __restrict__ in, const float* __restrict__ skip,
                                 float* __restrict__ out, int H, int W)
{
    int Ho = H * 2, Wo = W * 2;
    int total = B * 64 * Ho * Wo;
    int idx = blockIdx.x * blockDim.x + threadIdx.x;
    if (idx >= total) return;
    int xo = idx % Wo;
    int yo = (idx / Wo) % Ho;
    int c  = (idx / (Wo * Ho)) % 64;
    int b  = idx / (Wo * Ho * 64);

    float ys = (float)yo * (float)(H - 1) / (float)(Ho - 1);
    float xs = (float)xo * (float)(W - 1) / (float)(Wo - 1);
    int y0 = (int)floorf(ys); int y1 = min(y0 + 1, H - 1);
    int x0 = (int)floorf(xs); int x1 = min(x0 + 1, W - 1);
    float wy = ys - (float)y0, wx = xs - (float)x0;

    const float* p = in + ((size_t)b * 64 + c) * H * W;
    float r0 = p[y0 * W + x0] * (1.f - wy) + p[y1 * W + x0] * wy;
    float r1 = p[y0 * W + x1] * (1.f - wy) + p[y1 * W + x1] * wy;
    float v = r0 * (1.f - wx) + r1 * wx;

    size_t obase = (((size_t)b * 128 + c) * Ho + yo) * Wo + xo;
    out[obase] = v;
    out[obase + (size_t)64 * Ho * Wo] =
        skip[(((size_t)b * 64 + c) * Ho + yo) * Wo + xo];
}

// ---------------- final 1x1 conv (64->2) + residual + NCHW->NHWC ----------------
__global__ void final_kernel(const float* __restrict__ in, const float* __restrict__ zf,
                             const float* __restrict__ wbuf, int woff, int boff,
                             float* __restrict__ out)
{
    __shared__ float sw[130];
    int b  = blockIdx.y;
    int tid = threadIdx.x;
    const float* wb = wbuf + (size_t)b * OUTD;
    if (tid < 128) sw[tid] = wb[woff + tid];
    else if (tid < 130) sw[tid] = wb[boff + (tid - 128)];
    __syncthreads();
    int hw = blockIdx.x * 256 + tid;
    const float* inb = in + (size_t)b * 64 * 65536 + hw;
    float a0 = sw[128], a1 = sw[129];
#pragma unroll 8
    for (int c = 0; c < 64; c++) {
        float v = inb[(size_t)c * 65536];
        a0 = fmaf(v, sw[c], a0);
        a1 = fmaf(v, sw[64 + c], a1);
    }
    size_t o = ((size_t)b * 65536 + hw) * 2;
    out[o]     = zf[o]     + a0;
    out[o + 1] = zf[o + 1] + a1;
}

// ---------------- host side ----------------
static const int KOFF[15] = {0, 1152, 38016, 74880, 111744, 148608, 185472, 222336,
                             259200, 332928, 369792, 443520, 480384, 554112, 590976};
static const int CINL[15] = {2, 64, 64, 64, 64, 64, 64, 64, 128, 64, 128, 64, 128, 64, 64};
static const int WPOFF[14]= {0, 640, 21120, 41600, 62080, 82560, 103040, 123520,
                             144000, 184960, 205440, 246400, 266880, 307840};
#define BOFF(i) (591104 + 64 * (i))

static inline void launch_conv(const float* in, float* out, const float2* wp,
                               const float* wb, int layer, int H, int relu)
{
    int cin = CINL[layer];
    int tiles = (H / 32) * (H / 32);
    if (H <= 64) {
        dim3 gs(tiles, 8, B);   // OCB=8
        if (cin == 64)
            conv3x3_kernel<64, 8, false><<<gs, 256>>>(in, out, wp, wb, WPOFF[layer], BOFF(layer), H, relu);
        else
            conv3x3_kernel<128, 8, false><<<gs, 256>>>(in, out, wp, wb, WPOFF[layer], BOFF(layer), H, relu);
    } else {
        dim3 gs(tiles, 4, B);   // OCB=16
        if (cin == 2)
            conv3x3_kernel<2, 16, true><<<gs, 256>>>(in, out, wp, wb, WPOFF[layer], BOFF(layer), H, relu);
        else if (cin == 64)
            conv3x3_kernel<64, 16, false><<<gs, 256>>>(in, out, wp, wb, WPOFF[layer], BOFF(layer), H, relu);
        else
            conv3x3_kernel<128, 16, false><<<gs, 256>>>(in, out, wp, wb, WPOFF[layer], BOFF(layer), H, relu);
    }
}

extern "C" void kernel_launch(void* const* d_in, const int* in_sizes, int n_in,
                              void* d_out, int out_size)
{
    const float* zf = (const float*)d_in[0];
    const float* hp = (const float*)d_in[2];
    const float* W1 = (const float*)d_in[3];
    const float* b1 = (const float*)d_in[4];
    const float* W2 = (const float*)d_in[5];
    const float* b2 = (const float*)d_in[6];
    const float* Wo = (const float*)d_in[7];
    const float* bo = (const float*)d_in[8];
    float* out = (float*)d_out;
    float* l1 = out + (size_t)B * 256 * 256 * 2;

    float *pA, *pB, *pS1, *pS2, *pS3, *pW;
    float2* pWP;
    cudaGetSymbolAddress((void**)&pA,  g_bufA);
    cudaGetSymbolAddress((void**)&pB,  g_bufB);
    cudaGetSymbolAddress((void**)&pS1, g_skip1);
    cudaGetSymbolAddress((void**)&pS2, g_skip2);
    cudaGetSymbolAddress((void**)&pS3, g_skip3);
    cudaGetSymbolAddress((void**)&pW,  g_w);
    cudaGetSymbolAddress((void**)&pWP, g_wp);

    hyper1_kernel<<<1, 256>>>(hp, W1, b1, W2, b2, l1);
    weightgen_kernel<<<(OUTD + 255) / 256, 256>>>(Wo, bo, l1);
    repack_kernel<<<(B * 295488 + 255) / 256, 256>>>();

    // encoder (layer 0 reads zf NHWC directly)
    launch_conv(zf, pA, pWP, pW, 0, 256, 1);
    launch_conv(pA, pS1, pWP, pW, 1, 256, 1);
    { int n = B * 64 * 128 * 128; maxpool_kernel<<<(n + 255) / 256, 256>>>(pS1, pA, 256, 256); }
    launch_conv(pA, pB, pWP, pW, 2, 128, 1);
    launch_conv(pB, pS2, pWP, pW, 3, 128, 1);
    { int n = B * 64 * 64 * 64;   maxpool_kernel<<<(n + 255) / 256, 256>>>(pS2, pA, 128, 128); }
    launch_conv(pA, pB, pWP, pW, 4, 64, 1);
    launch_conv(pB, pS3, pWP, pW, 5, 64, 1);
    { int n = B * 64 * 32 * 32;   maxpool_kernel<<<(n + 255) / 256, 256>>>(pS3, pA, 64, 64); }
    launch_conv(pA, pB, pWP, pW, 6, 32, 1);
    launch_conv(pB, pA, pWP, pW, 7, 32, 1);

    // decoder level 1 (32 -> 64)
    { int n = B * 64 * 64 * 64;   up_concat_kernel<<<(n + 255) / 256, 256>>>(pA, pS3, pB, 32, 32); }
    launch_conv(pB, pA, pWP, pW, 8, 64, 1);
    launch_conv(pA, pB, pWP, pW, 9, 64, 1);

    // decoder level 2 (64 -> 128)
    { int n = B * 64 * 128 * 128; up_concat_kernel<<<(n + 255) / 256, 256>>>(pB, pS2, pA, 64, 64); }
    launch_conv(pA, pB, pWP, pW, 10, 128, 1);
    launch_conv(pB, pA, pWP, pW, 11, 128, 1);

    // decoder level 3 (128 -> 256)
    { int n = B * 64 * 256 * 256; up_concat_kernel<<<(n + 255) / 256, 256>>>(pA, pS1, pB, 128, 128); }
    launch_conv(pB, pA, pWP, pW, 12, 256, 1);
    launch_conv(pA, pB, pWP, pW, 13, 256, 1);

    {
        dim3 gs(65536 / 256, B);
        final_kernel<<<gs, 256>>>(pB, zf, pW, KOFF[14], BOFF(14), out);
    }
}